// round 7
// baseline (speedup 1.0000x reference)
#include <cuda_runtime.h>
#include <cstdint>

#define N_NODES_MAX 100000
#define N_EDGES_MAX 1600000
#define IN_F  256
#define OUT_F 128
#define SCAN_CHUNK 1024
#define MAX_SCAN_BLOCKS ((N_NODES_MAX + SCAN_CHUNK - 1) / SCAN_CHUNK)   // 98

// ---------------- device scratch ----------------
__device__ float g_h[(size_t)N_NODES_MAX * OUT_F];     // 51.2 MB: h = x @ w
__device__ int   g_counts[N_NODES_MAX];
__device__ int   g_rowstart[N_NODES_MAX];
__device__ int   g_cursor[N_NODES_MAX];
__device__ int   g_sorted_src[N_EDGES_MAX];
__device__ float g_sorted_w[N_EDGES_MAX];
__device__ int   g_blocksums[MAX_SCAN_BLOCKS];
__device__ int   g_blockoffs[MAX_SCAN_BLOCKS];

__device__ __forceinline__ int clamp_idx(int v, int n) {
    v = v < 0 ? 0 : v;
    return v >= n ? n - 1 : v;
}

// ------- 1) SGEMM half: g_h[:, ncol0:ncol0+64] = x @ w[:, ncol0:ncol0+64] ---
// BM=128, BN=64, BK=8, TM=TN=8, 128 threads (16x8 thread grid).
__global__ __launch_bounds__(128) void gemm64_kernel(
    const float* __restrict__ x, const float* __restrict__ w, int M, int ncol0)
{
    __shared__ float As[8][128];
    __shared__ float Bs[8][64];

    const int tid = threadIdx.x;
    const int block_row = blockIdx.x * 128;

    const int ty = tid >> 3;          // 0..15 -> rows ty*8..+8
    const int tx = tid & 7;           // 0..7  -> cols tx*8..+8

    // A-load: 2 float4 per thread; idx 0..255 -> r=idx/2, c=(idx&1)*4
    // B-load: 1 float4 per thread; kr=tid/16 (0..7), kc=(tid&15)*4
    const int br = tid >> 4;
    const int bc = (tid & 15) * 4;

    float acc[8][8];
#pragma unroll
    for (int i = 0; i < 8; i++)
#pragma unroll
        for (int j = 0; j < 8; j++) acc[i][j] = 0.0f;

    for (int kt = 0; kt < IN_F / 8; kt++) {
        const int kbase = kt * 8;
#pragma unroll
        for (int i = 0; i < 2; i++) {
            const int idx = tid * 2 + i;
            const int r = idx >> 1;
            const int c = (idx & 1) * 4;
            const int row = block_row + r;
            float4 av = make_float4(0.f, 0.f, 0.f, 0.f);
            if (row < M)
                av = *reinterpret_cast<const float4*>(x + (size_t)row * IN_F + kbase + c);
            As[c + 0][r] = av.x;
            As[c + 1][r] = av.y;
            As[c + 2][r] = av.z;
            As[c + 3][r] = av.w;
        }
        float4 bv = *reinterpret_cast<const float4*>(
            w + (size_t)(kbase + br) * OUT_F + ncol0 + bc);
        *reinterpret_cast<float4*>(&Bs[br][bc]) = bv;
        __syncthreads();

#pragma unroll
        for (int k = 0; k < 8; k++) {
            float4 a0 = *reinterpret_cast<float4*>(&As[k][ty * 8]);
            float4 a1 = *reinterpret_cast<float4*>(&As[k][ty * 8 + 4]);
            float4 b0 = *reinterpret_cast<float4*>(&Bs[k][tx * 8]);
            float4 b1 = *reinterpret_cast<float4*>(&Bs[k][tx * 8 + 4]);
            float ra[8] = {a0.x, a0.y, a0.z, a0.w, a1.x, a1.y, a1.z, a1.w};
            float rb[8] = {b0.x, b0.y, b0.z, b0.w, b1.x, b1.y, b1.z, b1.w};
#pragma unroll
            for (int i = 0; i < 8; i++)
#pragma unroll
                for (int j = 0; j < 8; j++) acc[i][j] += ra[i] * rb[j];
        }
        __syncthreads();
    }

#pragma unroll
    for (int i = 0; i < 8; i++) {
        const int row = block_row + ty * 8 + i;
        if (row < M) {
            float* o = g_h + (size_t)row * OUT_F + ncol0 + tx * 8;
            *reinterpret_cast<float4*>(o)     = make_float4(acc[i][0], acc[i][1], acc[i][2], acc[i][3]);
            *reinterpret_cast<float4*>(o + 4) = make_float4(acc[i][4], acc[i][5], acc[i][6], acc[i][7]);
        }
    }
}

// ---------------- 2) CSR build -----------------------------------------
__global__ void zero_counts_kernel(int n)
{
    int i = blockIdx.x * blockDim.x + threadIdx.x;
    if (i < n) g_counts[i] = 0;
}

__global__ void hist_kernel(const int* __restrict__ edst, int E, int n_nodes)
{
    int t = blockIdx.x * blockDim.x + threadIdx.x;
    int base = t * 4;
    if (base + 3 < E) {
        int4 d4 = *reinterpret_cast<const int4*>(edst + base);
        atomicAdd(&g_counts[clamp_idx(d4.x, n_nodes)], 1);
        atomicAdd(&g_counts[clamp_idx(d4.y, n_nodes)], 1);
        atomicAdd(&g_counts[clamp_idx(d4.z, n_nodes)], 1);
        atomicAdd(&g_counts[clamp_idx(d4.w, n_nodes)], 1);
    } else {
        for (int e = base; e < E; e++)
            atomicAdd(&g_counts[clamp_idx(edst[e], n_nodes)], 1);
    }
}

__global__ __launch_bounds__(1024) void scan_pass1(int n)
{
    __shared__ int warp_sums[32];
    const int tid = threadIdx.x;
    const int i = blockIdx.x * SCAN_CHUNK + tid;
    int v = (i < n) ? g_counts[i] : 0;
    int s = v;
#pragma unroll
    for (int off = 16; off > 0; off >>= 1) s += __shfl_down_sync(0xffffffffu, s, off);
    if ((tid & 31) == 0) warp_sums[tid >> 5] = s;
    __syncthreads();
    if (tid < 32) {
        int t = warp_sums[tid];
#pragma unroll
        for (int off = 16; off > 0; off >>= 1) t += __shfl_down_sync(0xffffffffu, t, off);
        if (tid == 0) g_blocksums[blockIdx.x] = t;
    }
}

__global__ __launch_bounds__(128) void scan_pass2(int nblocks)
{
    const int tid = threadIdx.x;
    int v = (tid < nblocks) ? g_blocksums[tid] : 0;
    int x = v;
#pragma unroll
    for (int off = 1; off < 32; off <<= 1) {
        int y = __shfl_up_sync(0xffffffffu, x, off);
        if ((tid & 31) >= off) x += y;
    }
    __shared__ int ws[4];
    if ((tid & 31) == 31) ws[tid >> 5] = x;
    __syncthreads();
    int add = 0;
    for (int wlt = 0; wlt < (tid >> 5); wlt++) add += ws[wlt];
    int incl = x + add;
    if (tid < nblocks) g_blockoffs[tid] = incl - v;
}

__global__ __launch_bounds__(1024) void scan_pass3(int n)
{
    __shared__ int warp_sums[32];
    const int tid = threadIdx.x;
    const int i = blockIdx.x * SCAN_CHUNK + tid;
    int v = (i < n) ? g_counts[i] : 0;
    int x = v;
#pragma unroll
    for (int off = 1; off < 32; off <<= 1) {
        int y = __shfl_up_sync(0xffffffffu, x, off);
        if ((tid & 31) >= off) x += y;
    }
    if ((tid & 31) == 31) warp_sums[tid >> 5] = x;
    __syncthreads();
    if (tid < 32) {
        int t = warp_sums[tid];
#pragma unroll
        for (int off = 1; off < 32; off <<= 1) {
            int y = __shfl_up_sync(0xffffffffu, t, off);
            if (tid >= off) t += y;
        }
        warp_sums[tid] = t;
    }
    __syncthreads();
    int warp_off = (tid >> 5) ? warp_sums[(tid >> 5) - 1] : 0;
    int excl = x - v + warp_off + g_blockoffs[blockIdx.x];
    if (i < n) {
        g_rowstart[i] = excl;
        g_cursor[i]   = excl;
    }
}

__global__ void fill_kernel(const int* __restrict__ esrc,
                            const int* __restrict__ edst,
                            const float* __restrict__ ew, int E, int n_nodes)
{
    int e = blockIdx.x * blockDim.x + threadIdx.x;
    if (e < E) {
        int d = clamp_idx(edst[e], n_nodes);
        int pos = atomicAdd(&g_cursor[d], 1);
        if (pos >= 0 && pos < N_EDGES_MAX) {
            g_sorted_src[pos] = clamp_idx(esrc[e], n_nodes);
            g_sorted_w[pos]   = ew[e];
        }
    }
}

// ------- 3) gather half: out[:, col0:col0+64], warp/node, float2/lane -------
__global__ __launch_bounds__(256) void gather_half_kernel(
    const float* __restrict__ b, float* __restrict__ out, int n_nodes, int col0)
{
    const int gtid = blockIdx.x * blockDim.x + threadIdx.x;
    const int node = gtid >> 5;
    const int lane = gtid & 31;
    if (node >= n_nodes) return;

    const int start = g_rowstart[node];
    const int cnt   = g_counts[node];
    const float* hbase = g_h + col0 + (size_t)lane * 2;

    float2 acc0 = make_float2(0.f, 0.f);
    float2 acc1 = make_float2(0.f, 0.f);

    int j = 0;
    for (; j + 4 <= cnt; j += 4) {
        const int   s0 = g_sorted_src[start + j + 0];
        const int   s1 = g_sorted_src[start + j + 1];
        const int   s2 = g_sorted_src[start + j + 2];
        const int   s3 = g_sorted_src[start + j + 3];
        const float w0 = g_sorted_w[start + j + 0];
        const float w1 = g_sorted_w[start + j + 1];
        const float w2 = g_sorted_w[start + j + 2];
        const float w3 = g_sorted_w[start + j + 3];
        const float2 v0 = *reinterpret_cast<const float2*>(hbase + (size_t)s0 * OUT_F);
        const float2 v1 = *reinterpret_cast<const float2*>(hbase + (size_t)s1 * OUT_F);
        const float2 v2 = *reinterpret_cast<const float2*>(hbase + (size_t)s2 * OUT_F);
        const float2 v3 = *reinterpret_cast<const float2*>(hbase + (size_t)s3 * OUT_F);
        acc0.x += w0 * v0.x; acc0.y += w0 * v0.y;
        acc1.x += w1 * v1.x; acc1.y += w1 * v1.y;
        acc0.x += w2 * v2.x; acc0.y += w2 * v2.y;
        acc1.x += w3 * v3.x; acc1.y += w3 * v3.y;
    }
    for (; j < cnt; j++) {
        const int   s  = g_sorted_src[start + j];
        const float wt = g_sorted_w[start + j];
        const float2 v = *reinterpret_cast<const float2*>(hbase + (size_t)s * OUT_F);
        acc0.x += wt * v.x; acc0.y += wt * v.y;
    }

    const float2 bb = *reinterpret_cast<const float2*>(b + col0 + lane * 2);
    float2 r;
    r.x = acc0.x + acc1.x + bb.x;
    r.y = acc0.y + acc1.y + bb.y;
    *reinterpret_cast<float2*>(out + (size_t)node * OUT_F + col0 + lane * 2) = r;
}

// ---------------------------- launch ---------------------------------------
extern "C" void kernel_launch(void* const* d_in, const int* in_sizes, int n_in,
                              void* d_out, int out_size)
{
    const float* x    = (const float*)d_in[0];
    const int*   esrc = (const int*)d_in[1];
    const int*   edst = (const int*)d_in[2];
    const float* ew   = (const float*)d_in[3];
    const float* w    = (const float*)d_in[4];
    const float* b    = (const float*)d_in[5];
    float*       out  = (float*)d_out;

    const int M = in_sizes[0] / IN_F;   // 100000
    const int E = in_sizes[1];          // 1600000
    const int nscan = (M + SCAN_CHUNK - 1) / SCAN_CHUNK;

    static cudaStream_t s_side = nullptr;
    static cudaEvent_t  e_fork = nullptr, e_fill = nullptr,
                        e_g0 = nullptr, e_g0done = nullptr;
    if (!s_side) {
        cudaStreamCreateWithFlags(&s_side, cudaStreamNonBlocking);
        cudaEventCreateWithFlags(&e_fork,   cudaEventDisableTiming);
        cudaEventCreateWithFlags(&e_fill,   cudaEventDisableTiming);
        cudaEventCreateWithFlags(&e_g0,     cudaEventDisableTiming);
        cudaEventCreateWithFlags(&e_g0done, cudaEventDisableTiming);
    }

    // fork
    cudaEventRecord(e_fork, 0);
    cudaStreamWaitEvent(s_side, e_fork, 0);

    // side: CSR build
    zero_counts_kernel<<<(M + 255) / 256, 256, 0, s_side>>>(M);
    hist_kernel<<<((E + 3) / 4 + 255) / 256, 256, 0, s_side>>>(edst, E, M);
    scan_pass1<<<nscan, 1024, 0, s_side>>>(M);
    scan_pass2<<<1, 128, 0, s_side>>>(nscan);
    scan_pass3<<<nscan, 1024, 0, s_side>>>(M);
    fill_kernel<<<(E + 255) / 256, 256, 0, s_side>>>(esrc, edst, ew, E, M);
    cudaEventRecord(e_fill, s_side);

    // main: GEMM half 0 (cols 0-63)
    gemm64_kernel<<<(M + 127) / 128, 128>>>(x, w, M, 0);
    cudaEventRecord(e_g0, 0);

    // main: GEMM half 1 (cols 64-127)   [overlaps gather0 on side]
    gemm64_kernel<<<(M + 127) / 128, 128>>>(x, w, M, 64);

    // side: gather half 0 (needs CSR fill + GEMM half 0)
    cudaStreamWaitEvent(s_side, e_g0, 0);
    gather_half_kernel<<<((M * 32) + 255) / 256, 256, 0, s_side>>>(b, out, M, 0);
    cudaEventRecord(e_g0done, s_side);

    // main: gather half 1 (needs CSR fill + GEMM half 1)
    cudaStreamWaitEvent(0, e_fill, 0);
    gather_half_kernel<<<((M * 32) + 255) / 256, 256>>>(b, out, M, 64);

    // join side before returning control to harness's stream
    cudaStreamWaitEvent(0, e_g0done, 0);
}

// round 8
// speedup vs baseline: 1.1542x; 1.1542x over previous
#include <cuda_runtime.h>
#include <cstdint>

#define N_NODES_MAX 100000
#define N_EDGES_MAX 1600000
#define IN_F  256
#define OUT_F 128
#define SCAN_CHUNK 1024
#define MAX_SCAN_BLOCKS ((N_NODES_MAX + SCAN_CHUNK - 1) / SCAN_CHUNK)   // 98

// ---------------- device scratch ----------------
__device__ float g_h[(size_t)N_NODES_MAX * OUT_F];     // 51.2 MB: h = x @ w
__device__ int   g_counts[N_NODES_MAX];
__device__ int   g_rowstart[N_NODES_MAX];
__device__ int   g_cursor[N_NODES_MAX];
__device__ int   g_sorted_src[N_EDGES_MAX];
__device__ float g_sorted_w[N_EDGES_MAX];
__device__ int   g_blocksums[MAX_SCAN_BLOCKS];
__device__ int   g_blockoffs[MAX_SCAN_BLOCKS];

__device__ __forceinline__ int clamp_idx(int v, int n) {
    v = v < 0 ? 0 : v;
    return v >= n ? n - 1 : v;
}

// ---------------- 1) SGEMM: g_h = x @ w, software-pipelined ----------------
// BM=128, BN=128, BK=8, TM=TN=8, 256 threads. Register prefetch of next tile.
__global__ __launch_bounds__(256) void gemm_kernel(
    const float* __restrict__ x, const float* __restrict__ w, int M)
{
    __shared__ float As[8][128];
    __shared__ float Bs[8][128];

    const int tid = threadIdx.x;
    const int block_row = blockIdx.x * 128;

    const int ty = tid >> 4;         // 0..15
    const int tx = tid & 15;         // 0..15

    const int ar = tid >> 1;         // A-load row 0..127
    const int ac = (tid & 1) * 4;    // 4 floats along K
    const int br = tid >> 5;         // B-load k-row 0..7
    const int bc = (tid & 31) * 4;   // 4 floats along N

    float acc[8][8];
#pragma unroll
    for (int i = 0; i < 8; i++)
#pragma unroll
        for (int j = 0; j < 8; j++) acc[i][j] = 0.0f;

    const int arow = block_row + ar;
    const bool arow_ok = (arow < M);
    const float* a_ptr = x + (size_t)arow * IN_F + ac;
    const float* b_ptr = w + (size_t)br * OUT_F + bc;

    // preload tile 0 into registers
    float4 av = make_float4(0.f, 0.f, 0.f, 0.f);
    if (arow_ok) av = *reinterpret_cast<const float4*>(a_ptr);
    float4 bv = *reinterpret_cast<const float4*>(b_ptr);

    const int NKT = IN_F / 8;        // 32
    for (int kt = 0; kt < NKT; kt++) {
        // commit prefetched tile to smem
        As[ac + 0][ar] = av.x;
        As[ac + 1][ar] = av.y;
        As[ac + 2][ar] = av.z;
        As[ac + 3][ar] = av.w;
        *reinterpret_cast<float4*>(&Bs[br][bc]) = bv;
        __syncthreads();

        // issue next tile's global loads (latency hidden by compute below)
        if (kt + 1 < NKT) {
            const int kbase = (kt + 1) * 8;
            if (arow_ok) av = *reinterpret_cast<const float4*>(a_ptr + kbase);
            bv = *reinterpret_cast<const float4*>(b_ptr + (size_t)kbase * OUT_F);
        }

#pragma unroll
        for (int k = 0; k < 8; k++) {
            float4 a0 = *reinterpret_cast<float4*>(&As[k][ty * 8]);
            float4 a1 = *reinterpret_cast<float4*>(&As[k][ty * 8 + 4]);
            float4 b0 = *reinterpret_cast<float4*>(&Bs[k][tx * 8]);
            float4 b1 = *reinterpret_cast<float4*>(&Bs[k][tx * 8 + 4]);
            float ra[8] = {a0.x, a0.y, a0.z, a0.w, a1.x, a1.y, a1.z, a1.w};
            float rb[8] = {b0.x, b0.y, b0.z, b0.w, b1.x, b1.y, b1.z, b1.w};
#pragma unroll
            for (int i = 0; i < 8; i++)
#pragma unroll
                for (int j = 0; j < 8; j++) acc[i][j] += ra[i] * rb[j];
        }
        __syncthreads();
    }

#pragma unroll
    for (int i = 0; i < 8; i++) {
        const int row = block_row + ty * 8 + i;
        if (row < M) {
            float* o = g_h + (size_t)row * OUT_F + tx * 8;
            *reinterpret_cast<float4*>(o)     = make_float4(acc[i][0], acc[i][1], acc[i][2], acc[i][3]);
            *reinterpret_cast<float4*>(o + 4) = make_float4(acc[i][4], acc[i][5], acc[i][6], acc[i][7]);
        }
    }
}

// ---------------- 2) CSR build -----------------------------------------
__global__ void zero_counts_kernel(int n)
{
    int i = blockIdx.x * blockDim.x + threadIdx.x;
    if (i < n) g_counts[i] = 0;
}

__global__ void hist_kernel(const int* __restrict__ edst, int E, int n_nodes)
{
    int t = blockIdx.x * blockDim.x + threadIdx.x;
    int base = t * 4;
    if (base + 3 < E) {
        int4 d4 = *reinterpret_cast<const int4*>(edst + base);
        atomicAdd(&g_counts[clamp_idx(d4.x, n_nodes)], 1);
        atomicAdd(&g_counts[clamp_idx(d4.y, n_nodes)], 1);
        atomicAdd(&g_counts[clamp_idx(d4.z, n_nodes)], 1);
        atomicAdd(&g_counts[clamp_idx(d4.w, n_nodes)], 1);
    } else {
        for (int e = base; e < E; e++)
            atomicAdd(&g_counts[clamp_idx(edst[e], n_nodes)], 1);
    }
}

__global__ __launch_bounds__(1024) void scan_pass1(int n)
{
    __shared__ int warp_sums[32];
    const int tid = threadIdx.x;
    const int i = blockIdx.x * SCAN_CHUNK + tid;
    int v = (i < n) ? g_counts[i] : 0;
    int s = v;
#pragma unroll
    for (int off = 16; off > 0; off >>= 1) s += __shfl_down_sync(0xffffffffu, s, off);
    if ((tid & 31) == 0) warp_sums[tid >> 5] = s;
    __syncthreads();
    if (tid < 32) {
        int t = warp_sums[tid];
#pragma unroll
        for (int off = 16; off > 0; off >>= 1) t += __shfl_down_sync(0xffffffffu, t, off);
        if (tid == 0) g_blocksums[blockIdx.x] = t;
    }
}

__global__ __launch_bounds__(128) void scan_pass2(int nblocks)
{
    const int tid = threadIdx.x;
    int v = (tid < nblocks) ? g_blocksums[tid] : 0;
    int x = v;
#pragma unroll
    for (int off = 1; off < 32; off <<= 1) {
        int y = __shfl_up_sync(0xffffffffu, x, off);
        if ((tid & 31) >= off) x += y;
    }
    __shared__ int ws[4];
    if ((tid & 31) == 31) ws[tid >> 5] = x;
    __syncthreads();
    int add = 0;
    for (int wlt = 0; wlt < (tid >> 5); wlt++) add += ws[wlt];
    int incl = x + add;
    if (tid < nblocks) g_blockoffs[tid] = incl - v;
}

__global__ __launch_bounds__(1024) void scan_pass3(int n)
{
    __shared__ int warp_sums[32];
    const int tid = threadIdx.x;
    const int i = blockIdx.x * SCAN_CHUNK + tid;
    int v = (i < n) ? g_counts[i] : 0;
    int x = v;
#pragma unroll
    for (int off = 1; off < 32; off <<= 1) {
        int y = __shfl_up_sync(0xffffffffu, x, off);
        if ((tid & 31) >= off) x += y;
    }
    if ((tid & 31) == 31) warp_sums[tid >> 5] = x;
    __syncthreads();
    if (tid < 32) {
        int t = warp_sums[tid];
#pragma unroll
        for (int off = 1; off < 32; off <<= 1) {
            int y = __shfl_up_sync(0xffffffffu, t, off);
            if (tid >= off) t += y;
        }
        warp_sums[tid] = t;
    }
    __syncthreads();
    int warp_off = (tid >> 5) ? warp_sums[(tid >> 5) - 1] : 0;
    int excl = x - v + warp_off + g_blockoffs[blockIdx.x];
    if (i < n) {
        g_rowstart[i] = excl;
        g_cursor[i]   = excl;
    }
}

__global__ void fill_kernel(const int* __restrict__ esrc,
                            const int* __restrict__ edst,
                            const float* __restrict__ ew, int E, int n_nodes)
{
    int e = blockIdx.x * blockDim.x + threadIdx.x;
    if (e < E) {
        int d = clamp_idx(edst[e], n_nodes);
        int pos = atomicAdd(&g_cursor[d], 1);
        if (pos >= 0 && pos < N_EDGES_MAX) {
            g_sorted_src[pos] = clamp_idx(esrc[e], n_nodes);
            g_sorted_w[pos]   = ew[e];
        }
    }
}

// ---------------- 3) gather: one warp per node, unrolled x4 ----------------
__global__ __launch_bounds__(256) void gather_kernel(
    const float* __restrict__ b, float* __restrict__ out, int n_nodes)
{
    const int gtid = blockIdx.x * blockDim.x + threadIdx.x;
    const int node = gtid >> 5;
    const int lane = gtid & 31;
    if (node >= n_nodes) return;

    const int start = g_rowstart[node];
    const int cnt   = g_counts[node];
    const float* hbase = g_h + (size_t)lane * 4;

    float4 acc0 = make_float4(0.f, 0.f, 0.f, 0.f);
    float4 acc1 = make_float4(0.f, 0.f, 0.f, 0.f);

    int j = 0;
    for (; j + 4 <= cnt; j += 4) {
        const int   s0 = g_sorted_src[start + j + 0];
        const int   s1 = g_sorted_src[start + j + 1];
        const int   s2 = g_sorted_src[start + j + 2];
        const int   s3 = g_sorted_src[start + j + 3];
        const float w0 = g_sorted_w[start + j + 0];
        const float w1 = g_sorted_w[start + j + 1];
        const float w2 = g_sorted_w[start + j + 2];
        const float w3 = g_sorted_w[start + j + 3];
        const float4 v0 = *reinterpret_cast<const float4*>(hbase + (size_t)s0 * OUT_F);
        const float4 v1 = *reinterpret_cast<const float4*>(hbase + (size_t)s1 * OUT_F);
        const float4 v2 = *reinterpret_cast<const float4*>(hbase + (size_t)s2 * OUT_F);
        const float4 v3 = *reinterpret_cast<const float4*>(hbase + (size_t)s3 * OUT_F);
        acc0.x += w0 * v0.x; acc0.y += w0 * v0.y; acc0.z += w0 * v0.z; acc0.w += w0 * v0.w;
        acc1.x += w1 * v1.x; acc1.y += w1 * v1.y; acc1.z += w1 * v1.z; acc1.w += w1 * v1.w;
        acc0.x += w2 * v2.x; acc0.y += w2 * v2.y; acc0.z += w2 * v2.z; acc0.w += w2 * v2.w;
        acc1.x += w3 * v3.x; acc1.y += w3 * v3.y; acc1.z += w3 * v3.z; acc1.w += w3 * v3.w;
    }
    for (; j < cnt; j++) {
        const int   s  = g_sorted_src[start + j];
        const float wt = g_sorted_w[start + j];
        const float4 v = *reinterpret_cast<const float4*>(hbase + (size_t)s * OUT_F);
        acc0.x += wt * v.x; acc0.y += wt * v.y; acc0.z += wt * v.z; acc0.w += wt * v.w;
    }

    const float4 bb = reinterpret_cast<const float4*>(b)[lane];
    float4 r;
    r.x = acc0.x + acc1.x + bb.x;
    r.y = acc0.y + acc1.y + bb.y;
    r.z = acc0.z + acc1.z + bb.z;
    r.w = acc0.w + acc1.w + bb.w;
    reinterpret_cast<float4*>(out)[(size_t)node * 32 + lane] = r;
}

// ---------------------------- launch ---------------------------------------
extern "C" void kernel_launch(void* const* d_in, const int* in_sizes, int n_in,
                              void* d_out, int out_size)
{
    const float* x    = (const float*)d_in[0];
    const int*   esrc = (const int*)d_in[1];
    const int*   edst = (const int*)d_in[2];
    const float* ew   = (const float*)d_in[3];
    const float* w    = (const float*)d_in[4];
    const float* b    = (const float*)d_in[5];
    float*       out  = (float*)d_out;

    const int M = in_sizes[0] / IN_F;   // 100000
    const int E = in_sizes[1];          // 1600000
    const int nscan = (M + SCAN_CHUNK - 1) / SCAN_CHUNK;

    static cudaStream_t s_side = nullptr;
    static cudaEvent_t  e_fork = nullptr, e_join = nullptr;
    if (!s_side) {
        cudaStreamCreateWithFlags(&s_side, cudaStreamNonBlocking);
        cudaEventCreateWithFlags(&e_fork, cudaEventDisableTiming);
        cudaEventCreateWithFlags(&e_join, cudaEventDisableTiming);
    }

    // fork: CSR build on side stream, GEMM on main stream
    cudaEventRecord(e_fork, 0);
    cudaStreamWaitEvent(s_side, e_fork, 0);

    gemm_kernel<<<(M + 127) / 128, 256>>>(x, w, M);

    zero_counts_kernel<<<(M + 255) / 256, 256, 0, s_side>>>(M);
    hist_kernel<<<((E + 3) / 4 + 255) / 256, 256, 0, s_side>>>(edst, E, M);
    scan_pass1<<<nscan, 1024, 0, s_side>>>(M);
    scan_pass2<<<1, 128, 0, s_side>>>(nscan);
    scan_pass3<<<nscan, 1024, 0, s_side>>>(M);
    fill_kernel<<<(E + 255) / 256, 256, 0, s_side>>>(esrc, edst, ew, E, M);

    // join: gather needs both GEMM (main) and CSR (side)
    cudaEventRecord(e_join, s_side);
    cudaStreamWaitEvent(0, e_join, 0);

    gather_kernel<<<((M * 32) + 255) / 256, 256>>>(b, out, M);
}

// round 9
// speedup vs baseline: 1.2367x; 1.0715x over previous
#include <cuda_runtime.h>
#include <cuda_fp16.h>
#include <cstdint>

#define N_NODES_MAX 100000
#define N_EDGES_MAX 1600000
#define IN_F  256
#define OUT_F 128
#define SCAN_CHUNK 1024
#define MAX_SCAN_BLOCKS ((N_NODES_MAX + SCAN_CHUNK - 1) / SCAN_CHUNK)   // 98

// ---------------- device scratch ----------------
__device__ __half2 g_h2[(size_t)N_NODES_MAX * (OUT_F / 2)];   // 25.6 MB: h fp16
__device__ int   g_counts[N_NODES_MAX];
__device__ int   g_rowstart[N_NODES_MAX];
__device__ int   g_cursor[N_NODES_MAX];
__device__ int   g_sorted_src[N_EDGES_MAX];
__device__ float g_sorted_w[N_EDGES_MAX];
__device__ int   g_blocksums[MAX_SCAN_BLOCKS];
__device__ int   g_blockoffs[MAX_SCAN_BLOCKS];

__device__ __forceinline__ int clamp_idx(int v, int n) {
    v = v < 0 ? 0 : v;
    return v >= n ? n - 1 : v;
}

// ---------------- 1) SGEMM: h = x @ w (fp32 math, fp16 store) --------------
// BM=128, BN=128, BK=8, TM=TN=8, 256 threads (proven R6 structure).
__global__ __launch_bounds__(256) void gemm_kernel(
    const float* __restrict__ x, const float* __restrict__ w, int M)
{
    __shared__ float As[8][128];
    __shared__ float Bs[8][128];

    const int tid = threadIdx.x;
    const int block_row = blockIdx.x * 128;

    const int ty = tid >> 4;
    const int tx = tid & 15;

    const int ar = tid >> 1;
    const int ac = (tid & 1) * 4;
    const int br = tid >> 5;
    const int bc = (tid & 31) * 4;

    float acc[8][8];
#pragma unroll
    for (int i = 0; i < 8; i++)
#pragma unroll
        for (int j = 0; j < 8; j++) acc[i][j] = 0.0f;

    const int arow = block_row + ar;
    const bool arow_ok = (arow < M);
    const float* a_ptr = x + (size_t)arow * IN_F + ac;

    for (int kt = 0; kt < IN_F / 8; kt++) {
        const int kbase = kt * 8;
        float4 av = make_float4(0.f, 0.f, 0.f, 0.f);
        if (arow_ok) av = *reinterpret_cast<const float4*>(a_ptr + kbase);
        As[ac + 0][ar] = av.x;
        As[ac + 1][ar] = av.y;
        As[ac + 2][ar] = av.z;
        As[ac + 3][ar] = av.w;
        float4 bv = *reinterpret_cast<const float4*>(w + (size_t)(kbase + br) * OUT_F + bc);
        *reinterpret_cast<float4*>(&Bs[br][bc]) = bv;
        __syncthreads();

#pragma unroll
        for (int k = 0; k < 8; k++) {
            float4 a0 = *reinterpret_cast<float4*>(&As[k][ty * 8]);
            float4 a1 = *reinterpret_cast<float4*>(&As[k][ty * 8 + 4]);
            float4 b0 = *reinterpret_cast<float4*>(&Bs[k][tx * 8]);
            float4 b1 = *reinterpret_cast<float4*>(&Bs[k][tx * 8 + 4]);
            float ra[8] = {a0.x, a0.y, a0.z, a0.w, a1.x, a1.y, a1.z, a1.w};
            float rb[8] = {b0.x, b0.y, b0.z, b0.w, b1.x, b1.y, b1.z, b1.w};
#pragma unroll
            for (int i = 0; i < 8; i++)
#pragma unroll
                for (int j = 0; j < 8; j++) acc[i][j] += ra[i] * rb[j];
        }
        __syncthreads();
    }

    // epilogue: fp32 -> fp16, 8 halves (16B) per row per thread
#pragma unroll
    for (int i = 0; i < 8; i++) {
        const int row = block_row + ty * 8 + i;
        if (row < M) {
            __half2 hv[4];
            hv[0] = __floats2half2_rn(acc[i][0], acc[i][1]);
            hv[1] = __floats2half2_rn(acc[i][2], acc[i][3]);
            hv[2] = __floats2half2_rn(acc[i][4], acc[i][5]);
            hv[3] = __floats2half2_rn(acc[i][6], acc[i][7]);
            *reinterpret_cast<float4*>(&g_h2[(size_t)row * (OUT_F / 2) + tx * 4]) =
                *reinterpret_cast<float4*>(hv);
        }
    }
}

// ---------------- 2) CSR build -----------------------------------------
__global__ void zero_counts_kernel(int n)
{
    int i = blockIdx.x * blockDim.x + threadIdx.x;
    if (i < n) g_counts[i] = 0;
}

__global__ void hist_kernel(const int* __restrict__ edst, int E, int n_nodes)
{
    int t = blockIdx.x * blockDim.x + threadIdx.x;
    int base = t * 4;
    if (base + 3 < E) {
        int4 d4 = *reinterpret_cast<const int4*>(edst + base);
        atomicAdd(&g_counts[clamp_idx(d4.x, n_nodes)], 1);
        atomicAdd(&g_counts[clamp_idx(d4.y, n_nodes)], 1);
        atomicAdd(&g_counts[clamp_idx(d4.z, n_nodes)], 1);
        atomicAdd(&g_counts[clamp_idx(d4.w, n_nodes)], 1);
    } else {
        for (int e = base; e < E; e++)
            atomicAdd(&g_counts[clamp_idx(edst[e], n_nodes)], 1);
    }
}

__global__ __launch_bounds__(1024) void scan_pass1(int n)
{
    __shared__ int warp_sums[32];
    const int tid = threadIdx.x;
    const int i = blockIdx.x * SCAN_CHUNK + tid;
    int v = (i < n) ? g_counts[i] : 0;
    int s = v;
#pragma unroll
    for (int off = 16; off > 0; off >>= 1) s += __shfl_down_sync(0xffffffffu, s, off);
    if ((tid & 31) == 0) warp_sums[tid >> 5] = s;
    __syncthreads();
    if (tid < 32) {
        int t = warp_sums[tid];
#pragma unroll
        for (int off = 16; off > 0; off >>= 1) t += __shfl_down_sync(0xffffffffu, t, off);
        if (tid == 0) g_blocksums[blockIdx.x] = t;
    }
}

__global__ __launch_bounds__(128) void scan_pass2(int nblocks)
{
    const int tid = threadIdx.x;
    int v = (tid < nblocks) ? g_blocksums[tid] : 0;
    int x = v;
#pragma unroll
    for (int off = 1; off < 32; off <<= 1) {
        int y = __shfl_up_sync(0xffffffffu, x, off);
        if ((tid & 31) >= off) x += y;
    }
    __shared__ int ws[4];
    if ((tid & 31) == 31) ws[tid >> 5] = x;
    __syncthreads();
    int add = 0;
    for (int wlt = 0; wlt < (tid >> 5); wlt++) add += ws[wlt];
    int incl = x + add;
    if (tid < nblocks) g_blockoffs[tid] = incl - v;
}

__global__ __launch_bounds__(1024) void scan_pass3(int n)
{
    __shared__ int warp_sums[32];
    const int tid = threadIdx.x;
    const int i = blockIdx.x * SCAN_CHUNK + tid;
    int v = (i < n) ? g_counts[i] : 0;
    int x = v;
#pragma unroll
    for (int off = 1; off < 32; off <<= 1) {
        int y = __shfl_up_sync(0xffffffffu, x, off);
        if ((tid & 31) >= off) x += y;
    }
    if ((tid & 31) == 31) warp_sums[tid >> 5] = x;
    __syncthreads();
    if (tid < 32) {
        int t = warp_sums[tid];
#pragma unroll
        for (int off = 1; off < 32; off <<= 1) {
            int y = __shfl_up_sync(0xffffffffu, t, off);
            if (tid >= off) t += y;
        }
        warp_sums[tid] = t;
    }
    __syncthreads();
    int warp_off = (tid >> 5) ? warp_sums[(tid >> 5) - 1] : 0;
    int excl = x - v + warp_off + g_blockoffs[blockIdx.x];
    if (i < n) {
        g_rowstart[i] = excl;
        g_cursor[i]   = excl;
    }
}

__global__ void fill_kernel(const int* __restrict__ esrc,
                            const int* __restrict__ edst,
                            const float* __restrict__ ew, int E, int n_nodes)
{
    int e = blockIdx.x * blockDim.x + threadIdx.x;
    if (e < E) {
        int d = clamp_idx(edst[e], n_nodes);
        int pos = atomicAdd(&g_cursor[d], 1);
        if (pos >= 0 && pos < N_EDGES_MAX) {
            g_sorted_src[pos] = clamp_idx(esrc[e], n_nodes);
            g_sorted_w[pos]   = ew[e];
        }
    }
}

// ------- 3) gather: warp/node, fp16 h rows (8B/lane/edge), unrolled x4 ------
__global__ __launch_bounds__(256) void gather_kernel(
    const float* __restrict__ b, float* __restrict__ out, int n_nodes)
{
    const int gtid = blockIdx.x * blockDim.x + threadIdx.x;
    const int node = gtid >> 5;
    const int lane = gtid & 31;
    if (node >= n_nodes) return;

    const int start = g_rowstart[node];
    const int cnt   = g_counts[node];
    const __half2* hbase = g_h2 + (size_t)lane * 2;   // 4 halves per lane

    float4 acc0 = make_float4(0.f, 0.f, 0.f, 0.f);
    float4 acc1 = make_float4(0.f, 0.f, 0.f, 0.f);

    int j = 0;
    for (; j + 4 <= cnt; j += 4) {
        const int   s0 = g_sorted_src[start + j + 0];
        const int   s1 = g_sorted_src[start + j + 1];
        const int   s2 = g_sorted_src[start + j + 2];
        const int   s3 = g_sorted_src[start + j + 3];
        const float w0 = g_sorted_w[start + j + 0];
        const float w1 = g_sorted_w[start + j + 1];
        const float w2 = g_sorted_w[start + j + 2];
        const float w3 = g_sorted_w[start + j + 3];
        const __half2* p0 = hbase + (size_t)s0 * (OUT_F / 2);
        const __half2* p1 = hbase + (size_t)s1 * (OUT_F / 2);
        const __half2* p2 = hbase + (size_t)s2 * (OUT_F / 2);
        const __half2* p3 = hbase + (size_t)s3 * (OUT_F / 2);
        float2 a, c;
        a = __half22float2(p0[0]); c = __half22float2(p0[1]);
        acc0.x += w0 * a.x; acc0.y += w0 * a.y; acc0.z += w0 * c.x; acc0.w += w0 * c.y;
        a = __half22float2(p1[0]); c = __half22float2(p1[1]);
        acc1.x += w1 * a.x; acc1.y += w1 * a.y; acc1.z += w1 * c.x; acc1.w += w1 * c.y;
        a = __half22float2(p2[0]); c = __half22float2(p2[1]);
        acc0.x += w2 * a.x; acc0.y += w2 * a.y; acc0.z += w2 * c.x; acc0.w += w2 * c.y;
        a = __half22float2(p3[0]); c = __half22float2(p3[1]);
        acc1.x += w3 * a.x; acc1.y += w3 * a.y; acc1.z += w3 * c.x; acc1.w += w3 * c.y;
    }
    for (; j < cnt; j++) {
        const int   s  = g_sorted_src[start + j];
        const float wt = g_sorted_w[start + j];
        const __half2* p = hbase + (size_t)s * (OUT_F / 2);
        float2 a = __half22float2(p[0]);
        float2 c = __half22float2(p[1]);
        acc0.x += wt * a.x; acc0.y += wt * a.y; acc0.z += wt * c.x; acc0.w += wt * c.y;
    }

    const float4 bb = reinterpret_cast<const float4*>(b)[lane];
    float4 r;
    r.x = acc0.x + acc1.x + bb.x;
    r.y = acc0.y + acc1.y + bb.y;
    r.z = acc0.z + acc1.z + bb.z;
    r.w = acc0.w + acc1.w + bb.w;
    reinterpret_cast<float4*>(out)[(size_t)node * 32 + lane] = r;
}

// ---------------------------- launch ---------------------------------------
extern "C" void kernel_launch(void* const* d_in, const int* in_sizes, int n_in,
                              void* d_out, int out_size)
{
    const float* x    = (const float*)d_in[0];
    const int*   esrc = (const int*)d_in[1];
    const int*   edst = (const int*)d_in[2];
    const float* ew   = (const float*)d_in[3];
    const float* w    = (const float*)d_in[4];
    const float* b    = (const float*)d_in[5];
    float*       out  = (float*)d_out;

    const int M = in_sizes[0] / IN_F;   // 100000
    const int E = in_sizes[1];          // 1600000
    const int nscan = (M + SCAN_CHUNK - 1) / SCAN_CHUNK;

    static cudaStream_t s_side = nullptr;
    static cudaEvent_t  e_fork = nullptr, e_join = nullptr;
    if (!s_side) {
        cudaStreamCreateWithFlags(&s_side, cudaStreamNonBlocking);
        cudaEventCreateWithFlags(&e_fork, cudaEventDisableTiming);
        cudaEventCreateWithFlags(&e_join, cudaEventDisableTiming);
    }

    // fork: CSR build on side stream, GEMM on main stream
    cudaEventRecord(e_fork, 0);
    cudaStreamWaitEvent(s_side, e_fork, 0);

    gemm_kernel<<<(M + 127) / 128, 256>>>(x, w, M);

    zero_counts_kernel<<<(M + 255) / 256, 256, 0, s_side>>>(M);
    hist_kernel<<<((E + 3) / 4 + 255) / 256, 256, 0, s_side>>>(edst, E, M);
    scan_pass1<<<nscan, 1024, 0, s_side>>>(M);
    scan_pass2<<<1, 128, 0, s_side>>>(nscan);
    scan_pass3<<<nscan, 1024, 0, s_side>>>(M);
    fill_kernel<<<(E + 255) / 256, 256, 0, s_side>>>(esrc, edst, ew, E, M);

    // join: gather needs both GEMM (main) and CSR (side)
    cudaEventRecord(e_join, s_side);
    cudaStreamWaitEvent(0, e_join, 0);

    gather_kernel<<<((M * 32) + 255) / 256, 256>>>(b, out, M);
}

// round 10
// speedup vs baseline: 1.7427x; 1.4091x over previous
#include <cuda_runtime.h>
#include <cuda_fp16.h>
#include <mma.h>
#include <cstdint>

using namespace nvcuda;

#define N_NODES_MAX 100000
#define N_EDGES_MAX 1600000
#define IN_F  256
#define OUT_F 128
#define SCAN_CHUNK 1024
#define MAX_SCAN_BLOCKS ((N_NODES_MAX + SCAN_CHUNK - 1) / SCAN_CHUNK)   // 98

#define GEMM_BM 128
#define GEMM_KC 32
#define GEMM_NCHUNK (IN_F / GEMM_KC)    // 8
#define LDA_S 40                        // A smem leading dim (halves), pads conflicts
#define LDE_S 20                        // epilogue staging leading dim (floats)

// ---------------- device scratch ----------------
__device__ __half2 g_h2[(size_t)N_NODES_MAX * (OUT_F / 2)];   // 25.6 MB h fp16
__device__ int   g_counts[N_NODES_MAX];
__device__ int   g_rowstart[N_NODES_MAX];
__device__ int   g_cursor[N_NODES_MAX];
__device__ int   g_sorted_src[N_EDGES_MAX];
__device__ float g_sorted_w[N_EDGES_MAX];
__device__ int   g_blocksums[MAX_SCAN_BLOCKS];
__device__ int   g_blockoffs[MAX_SCAN_BLOCKS];
__device__ __half g_w_h[IN_F * OUT_F];                        // w in fp16

__device__ __forceinline__ int clamp_idx(int v, int n) {
    v = v < 0 ? 0 : v;
    return v >= n ? n - 1 : v;
}

// ---------------- 0) prep: w -> fp16 ----------------------------------------
__global__ __launch_bounds__(256) void prep_w_kernel(const float* __restrict__ w)
{
    int e = blockIdx.x * blockDim.x + threadIdx.x;
    if (e < IN_F * OUT_F) g_w_h[e] = __float2half_rn(w[e]);
}

// ---------------- 1) fp16 WMMA GEMM: g_h2 = fp16(x @ w) ---------------------
// CTA 128x128, 256 threads = 8 warps (4 m x 2 n), warp tile 32x64.
__global__ __launch_bounds__(256) void gemm_wmma_kernel(const float* __restrict__ x, int M)
{
    // A/B tiles and epilogue staging share (live ranges disjoint, sync'd)
    __shared__ __half sA[GEMM_BM][LDA_S];            // 10240 B
    __shared__ __half sB[GEMM_KC][OUT_F];            //  8192 B
    __shared__ float  sE[8][16][LDE_S];              // 10240 B (reuses nothing; ok)

    const int tid = threadIdx.x;
    const int wid = tid >> 5;
    const int lane = tid & 31;
    const int warp_m = wid & 3;       // rows warp_m*32
    const int warp_n = wid >> 2;      // cols warp_n*64
    const int block_row = blockIdx.x * GEMM_BM;

    wmma::fragment<wmma::accumulator, 16, 16, 16, float> acc[2][4];
#pragma unroll
    for (int mi = 0; mi < 2; mi++)
#pragma unroll
        for (int ni = 0; ni < 4; ni++) wmma::fill_fragment(acc[mi][ni], 0.0f);

    for (int c = 0; c < GEMM_NCHUNK; c++) {
        const int k0 = c * GEMM_KC;
        // A: 128x32 floats -> fp16 smem. 1024 float4; 4 per thread.
#pragma unroll
        for (int i = 0; i < 4; i++) {
            const int idx = tid * 4 + i;
            const int r = idx >> 3;
            const int q = idx & 7;
            const int row = block_row + r;
            float4 v = make_float4(0.f, 0.f, 0.f, 0.f);
            if (row < M)
                v = *reinterpret_cast<const float4*>(x + (size_t)row * IN_F + k0 + q * 4);
            __half2* dst = reinterpret_cast<__half2*>(&sA[r][q * 4]);
            dst[0] = __floats2half2_rn(v.x, v.y);
            dst[1] = __floats2half2_rn(v.z, v.w);
        }
        // B: rows k0..k0+31 of g_w_h (8 KB) = 512 uint4; 2 per thread.
        {
            const uint4* src = reinterpret_cast<const uint4*>(g_w_h + k0 * OUT_F);
            uint4* dst = reinterpret_cast<uint4*>(&sB[0][0]);
            dst[tid]       = src[tid];
            dst[tid + 256] = src[tid + 256];
        }
        __syncthreads();

#pragma unroll
        for (int kk = 0; kk < GEMM_KC; kk += 16) {
            wmma::fragment<wmma::matrix_a, 16, 16, 16, __half, wmma::row_major> a[2];
#pragma unroll
            for (int mi = 0; mi < 2; mi++)
                wmma::load_matrix_sync(a[mi], &sA[warp_m * 32 + mi * 16][kk], LDA_S);
#pragma unroll
            for (int ni = 0; ni < 4; ni++) {
                wmma::fragment<wmma::matrix_b, 16, 16, 16, __half, wmma::row_major> bf;
                wmma::load_matrix_sync(bf, &sB[kk][warp_n * 64 + ni * 16], OUT_F);
#pragma unroll
                for (int mi = 0; mi < 2; mi++)
                    wmma::mma_sync(acc[mi][ni], a[mi], bf, acc[mi][ni]);
            }
        }
        __syncthreads();
    }

    // epilogue: stage fp32 accs in smem, emit fp16 to g_h2
#pragma unroll
    for (int mi = 0; mi < 2; mi++) {
#pragma unroll
        for (int ni = 0; ni < 4; ni++) {
            wmma::store_matrix_sync(&sE[wid][0][0], acc[mi][ni], LDE_S, wmma::mem_row_major);
            __syncwarp();
            // 256 floats / 32 lanes: lane -> r = lane>>1, 8 cols at (lane&1)*8
            const int r = lane >> 1;
            const int c0 = (lane & 1) * 8;
            const int row = block_row + warp_m * 32 + mi * 16 + r;
            if (row < M) {
                const float* s = &sE[wid][r][c0];
                __half2 hv[4];
                hv[0] = __floats2half2_rn(s[0], s[1]);
                hv[1] = __floats2half2_rn(s[2], s[3]);
                hv[2] = __floats2half2_rn(s[4], s[5]);
                hv[3] = __floats2half2_rn(s[6], s[7]);
                const int col = warp_n * 64 + ni * 16 + c0;
                *reinterpret_cast<float4*>(&g_h2[(size_t)row * (OUT_F / 2) + col / 2]) =
                    *reinterpret_cast<float4*>(hv);
            }
            __syncwarp();
        }
    }
}

// ---------------- 2) CSR build -----------------------------------------
__global__ void zero_counts_kernel(int n)
{
    int i = blockIdx.x * blockDim.x + threadIdx.x;
    if (i < n) g_counts[i] = 0;
}

__global__ void hist_kernel(const int* __restrict__ edst, int E, int n_nodes)
{
    int t = blockIdx.x * blockDim.x + threadIdx.x;
    int base = t * 4;
    if (base + 3 < E) {
        int4 d4 = *reinterpret_cast<const int4*>(edst + base);
        atomicAdd(&g_counts[clamp_idx(d4.x, n_nodes)], 1);
        atomicAdd(&g_counts[clamp_idx(d4.y, n_nodes)], 1);
        atomicAdd(&g_counts[clamp_idx(d4.z, n_nodes)], 1);
        atomicAdd(&g_counts[clamp_idx(d4.w, n_nodes)], 1);
    } else {
        for (int e = base; e < E; e++)
            atomicAdd(&g_counts[clamp_idx(edst[e], n_nodes)], 1);
    }
}

__global__ __launch_bounds__(1024) void scan_pass1(int n)
{
    __shared__ int warp_sums[32];
    const int tid = threadIdx.x;
    const int i = blockIdx.x * SCAN_CHUNK + tid;
    int v = (i < n) ? g_counts[i] : 0;
    int s = v;
#pragma unroll
    for (int off = 16; off > 0; off >>= 1) s += __shfl_down_sync(0xffffffffu, s, off);
    if ((tid & 31) == 0) warp_sums[tid >> 5] = s;
    __syncthreads();
    if (tid < 32) {
        int t = warp_sums[tid];
#pragma unroll
        for (int off = 16; off > 0; off >>= 1) t += __shfl_down_sync(0xffffffffu, t, off);
        if (tid == 0) g_blocksums[blockIdx.x] = t;
    }
}

__global__ __launch_bounds__(128) void scan_pass2(int nblocks)
{
    const int tid = threadIdx.x;
    int v = (tid < nblocks) ? g_blocksums[tid] : 0;
    int x = v;
#pragma unroll
    for (int off = 1; off < 32; off <<= 1) {
        int y = __shfl_up_sync(0xffffffffu, x, off);
        if ((tid & 31) >= off) x += y;
    }
    __shared__ int ws[4];
    if ((tid & 31) == 31) ws[tid >> 5] = x;
    __syncthreads();
    int add = 0;
    for (int wlt = 0; wlt < (tid >> 5); wlt++) add += ws[wlt];
    int incl = x + add;
    if (tid < nblocks) g_blockoffs[tid] = incl - v;
}

__global__ __launch_bounds__(1024) void scan_pass3(int n)
{
    __shared__ int warp_sums[32];
    const int tid = threadIdx.x;
    const int i = blockIdx.x * SCAN_CHUNK + tid;
    int v = (i < n) ? g_counts[i] : 0;
    int x = v;
#pragma unroll
    for (int off = 1; off < 32; off <<= 1) {
        int y = __shfl_up_sync(0xffffffffu, x, off);
        if ((tid & 31) >= off) x += y;
    }
    if ((tid & 31) == 31) warp_sums[tid >> 5] = x;
    __syncthreads();
    if (tid < 32) {
        int t = warp_sums[tid];
#pragma unroll
        for (int off = 1; off < 32; off <<= 1) {
            int y = __shfl_up_sync(0xffffffffu, t, off);
            if (tid >= off) t += y;
        }
        warp_sums[tid] = t;
    }
    __syncthreads();
    int warp_off = (tid >> 5) ? warp_sums[(tid >> 5) - 1] : 0;
    int excl = x - v + warp_off + g_blockoffs[blockIdx.x];
    if (i < n) {
        g_rowstart[i] = excl;
        g_cursor[i]   = excl;
    }
}

__global__ void fill_kernel(const int* __restrict__ esrc,
                            const int* __restrict__ edst,
                            const float* __restrict__ ew, int E, int n_nodes)
{
    int e = blockIdx.x * blockDim.x + threadIdx.x;
    if (e < E) {
        int d = clamp_idx(edst[e], n_nodes);
        int pos = atomicAdd(&g_cursor[d], 1);
        if (pos >= 0 && pos < N_EDGES_MAX) {
            g_sorted_src[pos] = clamp_idx(esrc[e], n_nodes);
            g_sorted_w[pos]   = ew[e];
        }
    }
}

// ------- 3) gather: warp/node, fp16 h rows (8B/lane/edge), unrolled x4 ------
__global__ __launch_bounds__(256) void gather_kernel(
    const float* __restrict__ b, float* __restrict__ out, int n_nodes)
{
    const int gtid = blockIdx.x * blockDim.x + threadIdx.x;
    const int node = gtid >> 5;
    const int lane = gtid & 31;
    if (node >= n_nodes) return;

    const int start = g_rowstart[node];
    const int cnt   = g_counts[node];
    const __half2* hbase = g_h2 + (size_t)lane * 2;

    float4 acc0 = make_float4(0.f, 0.f, 0.f, 0.f);
    float4 acc1 = make_float4(0.f, 0.f, 0.f, 0.f);

    int j = 0;
    for (; j + 4 <= cnt; j += 4) {
        const int   s0 = g_sorted_src[start + j + 0];
        const int   s1 = g_sorted_src[start + j + 1];
        const int   s2 = g_sorted_src[start + j + 2];
        const int   s3 = g_sorted_src[start + j + 3];
        const float w0 = g_sorted_w[start + j + 0];
        const float w1 = g_sorted_w[start + j + 1];
        const float w2 = g_sorted_w[start + j + 2];
        const float w3 = g_sorted_w[start + j + 3];
        const __half2* p0 = hbase + (size_t)s0 * (OUT_F / 2);
        const __half2* p1 = hbase + (size_t)s1 * (OUT_F / 2);
        const __half2* p2 = hbase + (size_t)s2 * (OUT_F / 2);
        const __half2* p3 = hbase + (size_t)s3 * (OUT_F / 2);
        float2 a, c;
        a = __half22float2(p0[0]); c = __half22float2(p0[1]);
        acc0.x += w0 * a.x; acc0.y += w0 * a.y; acc0.z += w0 * c.x; acc0.w += w0 * c.y;
        a = __half22float2(p1[0]); c = __half22float2(p1[1]);
        acc1.x += w1 * a.x; acc1.y += w1 * a.y; acc1.z += w1 * c.x; acc1.w += w1 * c.y;
        a = __half22float2(p2[0]); c = __half22float2(p2[1]);
        acc0.x += w2 * a.x; acc0.y += w2 * a.y; acc0.z += w2 * c.x; acc0.w += w2 * c.y;
        a = __half22float2(p3[0]); c = __half22float2(p3[1]);
        acc1.x += w3 * a.x; acc1.y += w3 * a.y; acc1.z += w3 * c.x; acc1.w += w3 * c.y;
    }
    for (; j < cnt; j++) {
        const int   s  = g_sorted_src[start + j];
        const float wt = g_sorted_w[start + j];
        const __half2* p = hbase + (size_t)s * (OUT_F / 2);
        float2 a = __half22float2(p[0]);
        float2 c = __half22float2(p[1]);
        acc0.x += wt * a.x; acc0.y += wt * a.y; acc0.z += wt * c.x; acc0.w += wt * c.y;
    }

    const float4 bb = reinterpret_cast<const float4*>(b)[lane];
    float4 r;
    r.x = acc0.x + acc1.x + bb.x;
    r.y = acc0.y + acc1.y + bb.y;
    r.z = acc0.z + acc1.z + bb.z;
    r.w = acc0.w + acc1.w + bb.w;
    reinterpret_cast<float4*>(out)[(size_t)node * 32 + lane] = r;
}

// ---------------------------- launch ---------------------------------------
extern "C" void kernel_launch(void* const* d_in, const int* in_sizes, int n_in,
                              void* d_out, int out_size)
{
    const float* x    = (const float*)d_in[0];
    const int*   esrc = (const int*)d_in[1];
    const int*   edst = (const int*)d_in[2];
    const float* ew   = (const float*)d_in[3];
    const float* w    = (const float*)d_in[4];
    const float* b    = (const float*)d_in[5];
    float*       out  = (float*)d_out;

    const int M = in_sizes[0] / IN_F;   // 100000
    const int E = in_sizes[1];          // 1600000
    const int nscan = (M + SCAN_CHUNK - 1) / SCAN_CHUNK;

    static cudaStream_t s_side = nullptr;
    static cudaEvent_t  e_fork = nullptr, e_join = nullptr;
    if (!s_side) {
        cudaStreamCreateWithFlags(&s_side, cudaStreamNonBlocking);
        cudaEventCreateWithFlags(&e_fork, cudaEventDisableTiming);
        cudaEventCreateWithFlags(&e_join, cudaEventDisableTiming);
    }

    // fork: CSR build on side stream, GEMM on main stream
    cudaEventRecord(e_fork, 0);
    cudaStreamWaitEvent(s_side, e_fork, 0);

    prep_w_kernel<<<(IN_F * OUT_F + 255) / 256, 256>>>(w);
    gemm_wmma_kernel<<<(M + GEMM_BM - 1) / GEMM_BM, 256>>>(x, M);

    zero_counts_kernel<<<(M + 255) / 256, 256, 0, s_side>>>(M);
    hist_kernel<<<((E + 3) / 4 + 255) / 256, 256, 0, s_side>>>(edst, E, M);
    scan_pass1<<<nscan, 1024, 0, s_side>>>(M);
    scan_pass2<<<1, 128, 0, s_side>>>(nscan);
    scan_pass3<<<nscan, 1024, 0, s_side>>>(M);
    fill_kernel<<<(E + 255) / 256, 256, 0, s_side>>>(esrc, edst, ew, E, M);

    // join: gather needs both GEMM (main) and CSR (side)
    cudaEventRecord(e_join, s_side);
    cudaStreamWaitEvent(0, e_join, 0);

    gather_kernel<<<((M * 32) + 255) / 256, 256>>>(b, out, M);
}

// round 11
// speedup vs baseline: 1.7939x; 1.0294x over previous
#include <cuda_runtime.h>
#include <cuda_fp16.h>
#include <mma.h>
#include <cstdint>

using namespace nvcuda;

#define N_NODES_MAX 100000
#define N_EDGES_MAX 1600000
#define IN_F  256
#define OUT_F 128
#define SCAN_CHUNK 1024
#define MAX_SCAN_BLOCKS ((N_NODES_MAX + SCAN_CHUNK - 1) / SCAN_CHUNK)   // 98

#define GEMM_BM 128
#define GEMM_KC 32
#define GEMM_NCHUNK (IN_F / GEMM_KC)    // 8
#define LDA_S 40                        // A smem leading dim (halves)
#define LDE_S 20                        // epilogue staging leading dim (floats)

// smem carve-up (bytes)
#define SA_BYTES (GEMM_BM * LDA_S * 2)          // 10240 per buffer
#define SB_BYTES (GEMM_KC * OUT_F * 2)          //  8192 per buffer
#define SMEM_RAW (2 * SA_BYTES + 2 * SB_BYTES)  // 36864

// ---------------- device scratch ----------------
__device__ __half2 g_h2[(size_t)N_NODES_MAX * (OUT_F / 2)];   // 25.6 MB h fp16
__device__ int   g_counts[N_NODES_MAX];
__device__ int   g_rowstart[N_NODES_MAX];
__device__ int   g_cursor[N_NODES_MAX];
__device__ int   g_sorted_src[N_EDGES_MAX];
__device__ float g_sorted_w[N_EDGES_MAX];
__device__ int   g_blocksums[MAX_SCAN_BLOCKS];
__device__ int   g_blockoffs[MAX_SCAN_BLOCKS];
__device__ __half g_w_h[IN_F * OUT_F];                        // w in fp16

__device__ __forceinline__ int clamp_idx(int v, int n) {
    v = v < 0 ? 0 : v;
    return v >= n ? n - 1 : v;
}

// ---------------- 0) prep: w -> fp16 ----------------------------------------
__global__ __launch_bounds__(256) void prep_w_kernel(const float* __restrict__ w)
{
    int e = blockIdx.x * blockDim.x + threadIdx.x;
    if (e < IN_F * OUT_F) g_w_h[e] = __float2half_rn(w[e]);
}

// ---------------- 1) fp16 WMMA GEMM, double-buffered ------------------------
// CTA 128x128, 256 threads = 8 warps (4 m x 2 n), warp tile 32x64.
__global__ __launch_bounds__(256) void gemm_wmma_kernel(const float* __restrict__ x, int M)
{
    __shared__ __align__(16) char smem_raw[SMEM_RAW];
    __half (*sA)[GEMM_BM][LDA_S] =
        reinterpret_cast<__half (*)[GEMM_BM][LDA_S]>(smem_raw);
    __half (*sB)[GEMM_KC][OUT_F] =
        reinterpret_cast<__half (*)[GEMM_KC][OUT_F]>(smem_raw + 2 * SA_BYTES);

    const int tid = threadIdx.x;
    const int wid = tid >> 5;
    const int lane = tid & 31;
    const int warp_m = wid & 3;
    const int warp_n = wid >> 2;
    const int block_row = blockIdx.x * GEMM_BM;

    // per-thread load mapping (A): idx = tid*4+i -> row idx/8, float4 slot idx%8
    const int r_ld[4] = { (tid * 4 + 0) >> 3, (tid * 4 + 1) >> 3,
                          (tid * 4 + 2) >> 3, (tid * 4 + 3) >> 3 };
    const int q_ld[4] = { (tid * 4 + 0) & 7, (tid * 4 + 1) & 7,
                          (tid * 4 + 2) & 7, (tid * 4 + 3) & 7 };

    wmma::fragment<wmma::accumulator, 16, 16, 16, float> acc[2][4];
#pragma unroll
    for (int mi = 0; mi < 2; mi++)
#pragma unroll
        for (int ni = 0; ni < 4; ni++) wmma::fill_fragment(acc[mi][ni], 0.0f);

    float4 a_reg[4];
    uint4  b_reg[2];

    // ---- load chunk 0 ----
#pragma unroll
    for (int i = 0; i < 4; i++) {
        const int row = block_row + r_ld[i];
        a_reg[i] = make_float4(0.f, 0.f, 0.f, 0.f);
        if (row < M)
            a_reg[i] = *reinterpret_cast<const float4*>(x + (size_t)row * IN_F + q_ld[i] * 4);
    }
    {
        const uint4* src = reinterpret_cast<const uint4*>(g_w_h);
        b_reg[0] = src[tid];
        b_reg[1] = src[tid + 256];
    }
    // ---- store chunk 0 to buffer 0 ----
#pragma unroll
    for (int i = 0; i < 4; i++) {
        __half2* dst = reinterpret_cast<__half2*>(&sA[0][r_ld[i]][q_ld[i] * 4]);
        dst[0] = __floats2half2_rn(a_reg[i].x, a_reg[i].y);
        dst[1] = __floats2half2_rn(a_reg[i].z, a_reg[i].w);
    }
    {
        uint4* dst = reinterpret_cast<uint4*>(&sB[0][0][0]);
        dst[tid]       = b_reg[0];
        dst[tid + 256] = b_reg[1];
    }
    __syncthreads();

    for (int c = 0; c < GEMM_NCHUNK; c++) {
        const int buf = c & 1;
        // issue next chunk's global loads
        if (c + 1 < GEMM_NCHUNK) {
            const int k0 = (c + 1) * GEMM_KC;
#pragma unroll
            for (int i = 0; i < 4; i++) {
                const int row = block_row + r_ld[i];
                a_reg[i] = make_float4(0.f, 0.f, 0.f, 0.f);
                if (row < M)
                    a_reg[i] = *reinterpret_cast<const float4*>(
                        x + (size_t)row * IN_F + k0 + q_ld[i] * 4);
            }
            const uint4* src = reinterpret_cast<const uint4*>(g_w_h + k0 * OUT_F);
            b_reg[0] = src[tid];
            b_reg[1] = src[tid + 256];
        }

        // compute current buffer
#pragma unroll
        for (int kk = 0; kk < GEMM_KC; kk += 16) {
            wmma::fragment<wmma::matrix_a, 16, 16, 16, __half, wmma::row_major> a[2];
#pragma unroll
            for (int mi = 0; mi < 2; mi++)
                wmma::load_matrix_sync(a[mi], &sA[buf][warp_m * 32 + mi * 16][kk], LDA_S);
#pragma unroll
            for (int ni = 0; ni < 4; ni++) {
                wmma::fragment<wmma::matrix_b, 16, 16, 16, __half, wmma::row_major> bf;
                wmma::load_matrix_sync(bf, &sB[buf][kk][warp_n * 64 + ni * 16], OUT_F);
#pragma unroll
                for (int mi = 0; mi < 2; mi++)
                    wmma::mma_sync(acc[mi][ni], a[mi], bf, acc[mi][ni]);
            }
        }

        // store next chunk into alternate buffer
        if (c + 1 < GEMM_NCHUNK) {
            const int nbuf = (c + 1) & 1;
#pragma unroll
            for (int i = 0; i < 4; i++) {
                __half2* dst = reinterpret_cast<__half2*>(&sA[nbuf][r_ld[i]][q_ld[i] * 4]);
                dst[0] = __floats2half2_rn(a_reg[i].x, a_reg[i].y);
                dst[1] = __floats2half2_rn(a_reg[i].z, a_reg[i].w);
            }
            uint4* dst = reinterpret_cast<uint4*>(&sB[nbuf][0][0]);
            dst[tid]       = b_reg[0];
            dst[tid + 256] = b_reg[1];
            __syncthreads();
        }
    }

    // epilogue: stage fp32 accs through smem (aliases A buffers), emit fp16
    __syncthreads();
    float* sE = reinterpret_cast<float*>(smem_raw) + wid * (16 * LDE_S);
#pragma unroll
    for (int mi = 0; mi < 2; mi++) {
#pragma unroll
        for (int ni = 0; ni < 4; ni++) {
            wmma::store_matrix_sync(sE, acc[mi][ni], LDE_S, wmma::mem_row_major);
            __syncwarp();
            const int r = lane >> 1;
            const int c0 = (lane & 1) * 8;
            const int row = block_row + warp_m * 32 + mi * 16 + r;
            if (row < M) {
                const float* s = sE + r * LDE_S + c0;
                __half2 hv[4];
                hv[0] = __floats2half2_rn(s[0], s[1]);
                hv[1] = __floats2half2_rn(s[2], s[3]);
                hv[2] = __floats2half2_rn(s[4], s[5]);
                hv[3] = __floats2half2_rn(s[6], s[7]);
                const int col = warp_n * 64 + ni * 16 + c0;
                *reinterpret_cast<float4*>(&g_h2[(size_t)row * (OUT_F / 2) + col / 2]) =
                    *reinterpret_cast<float4*>(hv);
            }
            __syncwarp();
        }
    }
}

// ---------------- 2) CSR build -----------------------------------------
__global__ void zero_counts_kernel(int n)
{
    int i = blockIdx.x * blockDim.x + threadIdx.x;
    if (i < n) g_counts[i] = 0;
}

__global__ void hist_kernel(const int* __restrict__ edst, int E, int n_nodes)
{
    int t = blockIdx.x * blockDim.x + threadIdx.x;
    int base = t * 4;
    if (base + 3 < E) {
        int4 d4 = *reinterpret_cast<const int4*>(edst + base);
        atomicAdd(&g_counts[clamp_idx(d4.x, n_nodes)], 1);
        atomicAdd(&g_counts[clamp_idx(d4.y, n_nodes)], 1);
        atomicAdd(&g_counts[clamp_idx(d4.z, n_nodes)], 1);
        atomicAdd(&g_counts[clamp_idx(d4.w, n_nodes)], 1);
    } else {
        for (int e = base; e < E; e++)
            atomicAdd(&g_counts[clamp_idx(edst[e], n_nodes)], 1);
    }
}

__global__ __launch_bounds__(1024) void scan_pass1(int n)
{
    __shared__ int warp_sums[32];
    const int tid = threadIdx.x;
    const int i = blockIdx.x * SCAN_CHUNK + tid;
    int v = (i < n) ? g_counts[i] : 0;
    int s = v;
#pragma unroll
    for (int off = 16; off > 0; off >>= 1) s += __shfl_down_sync(0xffffffffu, s, off);
    if ((tid & 31) == 0) warp_sums[tid >> 5] = s;
    __syncthreads();
    if (tid < 32) {
        int t = warp_sums[tid];
#pragma unroll
        for (int off = 16; off > 0; off >>= 1) t += __shfl_down_sync(0xffffffffu, t, off);
        if (tid == 0) g_blocksums[blockIdx.x] = t;
    }
}

__global__ __launch_bounds__(128) void scan_pass2(int nblocks)
{
    const int tid = threadIdx.x;
    int v = (tid < nblocks) ? g_blocksums[tid] : 0;
    int x = v;
#pragma unroll
    for (int off = 1; off < 32; off <<= 1) {
        int y = __shfl_up_sync(0xffffffffu, x, off);
        if ((tid & 31) >= off) x += y;
    }
    __shared__ int ws[4];
    if ((tid & 31) == 31) ws[tid >> 5] = x;
    __syncthreads();
    int add = 0;
    for (int wlt = 0; wlt < (tid >> 5); wlt++) add += ws[wlt];
    int incl = x + add;
    if (tid < nblocks) g_blockoffs[tid] = incl - v;
}

__global__ __launch_bounds__(1024) void scan_pass3(int n)
{
    __shared__ int warp_sums[32];
    const int tid = threadIdx.x;
    const int i = blockIdx.x * SCAN_CHUNK + tid;
    int v = (i < n) ? g_counts[i] : 0;
    int x = v;
#pragma unroll
    for (int off = 1; off < 32; off <<= 1) {
        int y = __shfl_up_sync(0xffffffffu, x, off);
        if ((tid & 31) >= off) x += y;
    }
    if ((tid & 31) == 31) warp_sums[tid >> 5] = x;
    __syncthreads();
    if (tid < 32) {
        int t = warp_sums[tid];
#pragma unroll
        for (int off = 1; off < 32; off <<= 1) {
            int y = __shfl_up_sync(0xffffffffu, t, off);
            if (tid >= off) t += y;
        }
        warp_sums[tid] = t;
    }
    __syncthreads();
    int warp_off = (tid >> 5) ? warp_sums[(tid >> 5) - 1] : 0;
    int excl = x - v + warp_off + g_blockoffs[blockIdx.x];
    if (i < n) {
        g_rowstart[i] = excl;
        g_cursor[i]   = excl;
    }
}

__global__ void fill_kernel(const int* __restrict__ esrc,
                            const int* __restrict__ edst,
                            const float* __restrict__ ew, int E, int n_nodes)
{
    int e = blockIdx.x * blockDim.x + threadIdx.x;
    if (e < E) {
        int d = clamp_idx(edst[e], n_nodes);
        int pos = atomicAdd(&g_cursor[d], 1);
        if (pos >= 0 && pos < N_EDGES_MAX) {
            g_sorted_src[pos] = clamp_idx(esrc[e], n_nodes);
            g_sorted_w[pos]   = ew[e];
        }
    }
}

// ------- 3) gather: warp/node, fp16 h rows (8B/lane/edge), unrolled x4 ------
__global__ __launch_bounds__(256) void gather_kernel(
    const float* __restrict__ b, float* __restrict__ out, int n_nodes)
{
    const int gtid = blockIdx.x * blockDim.x + threadIdx.x;
    const int node = gtid >> 5;
    const int lane = gtid & 31;
    if (node >= n_nodes) return;

    const int start = g_rowstart[node];
    const int cnt   = g_counts[node];
    const __half2* hbase = g_h2 + (size_t)lane * 2;

    float4 acc0 = make_float4(0.f, 0.f, 0.f, 0.f);
    float4 acc1 = make_float4(0.f, 0.f, 0.f, 0.f);

    int j = 0;
    for (; j + 4 <= cnt; j += 4) {
        const int   s0 = g_sorted_src[start + j + 0];
        const int   s1 = g_sorted_src[start + j + 1];
        const int   s2 = g_sorted_src[start + j + 2];
        const int   s3 = g_sorted_src[start + j + 3];
        const float w0 = g_sorted_w[start + j + 0];
        const float w1 = g_sorted_w[start + j + 1];
        const float w2 = g_sorted_w[start + j + 2];
        const float w3 = g_sorted_w[start + j + 3];
        const __half2* p0 = hbase + (size_t)s0 * (OUT_F / 2);
        const __half2* p1 = hbase + (size_t)s1 * (OUT_F / 2);
        const __half2* p2 = hbase + (size_t)s2 * (OUT_F / 2);
        const __half2* p3 = hbase + (size_t)s3 * (OUT_F / 2);
        float2 a, c;
        a = __half22float2(p0[0]); c = __half22float2(p0[1]);
        acc0.x += w0 * a.x; acc0.y += w0 * a.y; acc0.z += w0 * c.x; acc0.w += w0 * c.y;
        a = __half22float2(p1[0]); c = __half22float2(p1[1]);
        acc1.x += w1 * a.x; acc1.y += w1 * a.y; acc1.z += w1 * c.x; acc1.w += w1 * c.y;
        a = __half22float2(p2[0]); c = __half22float2(p2[1]);
        acc0.x += w2 * a.x; acc0.y += w2 * a.y; acc0.z += w2 * c.x; acc0.w += w2 * c.y;
        a = __half22float2(p3[0]); c = __half22float2(p3[1]);
        acc1.x += w3 * a.x; acc1.y += w3 * a.y; acc1.z += w3 * c.x; acc1.w += w3 * c.y;
    }
    for (; j < cnt; j++) {
        const int   s  = g_sorted_src[start + j];
        const float wt = g_sorted_w[start + j];
        const __half2* p = hbase + (size_t)s * (OUT_F / 2);
        float2 a = __half22float2(p[0]);
        float2 c = __half22float2(p[1]);
        acc0.x += wt * a.x; acc0.y += wt * a.y; acc0.z += wt * c.x; acc0.w += wt * c.y;
    }

    const float4 bb = reinterpret_cast<const float4*>(b)[lane];
    float4 r;
    r.x = acc0.x + acc1.x + bb.x;
    r.y = acc0.y + acc1.y + bb.y;
    r.z = acc0.z + acc1.z + bb.z;
    r.w = acc0.w + acc1.w + bb.w;
    reinterpret_cast<float4*>(out)[(size_t)node * 32 + lane] = r;
}

// ---------------------------- launch ---------------------------------------
extern "C" void kernel_launch(void* const* d_in, const int* in_sizes, int n_in,
                              void* d_out, int out_size)
{
    const float* x    = (const float*)d_in[0];
    const int*   esrc = (const int*)d_in[1];
    const int*   edst = (const int*)d_in[2];
    const float* ew   = (const float*)d_in[3];
    const float* w    = (const float*)d_in[4];
    const float* b    = (const float*)d_in[5];
    float*       out  = (float*)d_out;

    const int M = in_sizes[0] / IN_F;   // 100000
    const int E = in_sizes[1];          // 1600000
    const int nscan = (M + SCAN_CHUNK - 1) / SCAN_CHUNK;

    static cudaStream_t s_side = nullptr;
    static cudaEvent_t  e_fork = nullptr, e_join = nullptr;
    if (!s_side) {
        cudaStreamCreateWithFlags(&s_side, cudaStreamNonBlocking);
        cudaEventCreateWithFlags(&e_fork, cudaEventDisableTiming);
        cudaEventCreateWithFlags(&e_join, cudaEventDisableTiming);
    }

    // fork: CSR build on side stream, GEMM on main stream
    cudaEventRecord(e_fork, 0);
    cudaStreamWaitEvent(s_side, e_fork, 0);

    prep_w_kernel<<<(IN_F * OUT_F + 255) / 256, 256>>>(w);
    gemm_wmma_kernel<<<(M + GEMM_BM - 1) / GEMM_BM, 256>>>(x, M);

    zero_counts_kernel<<<(M + 255) / 256, 256, 0, s_side>>>(M);
    hist_kernel<<<((E + 3) / 4 + 255) / 256, 256, 0, s_side>>>(edst, E, M);
    scan_pass1<<<nscan, 1024, 0, s_side>>>(M);
    scan_pass2<<<1, 128, 0, s_side>>>(nscan);
    scan_pass3<<<nscan, 1024, 0, s_side>>>(M);
    fill_kernel<<<(E + 255) / 256, 256, 0, s_side>>>(esrc, edst, ew, E, M);

    // join: gather needs both GEMM (main) and CSR (side)
    cudaEventRecord(e_join, s_side);
    cudaStreamWaitEvent(0, e_join, 0);

    gather_kernel<<<((M * 32) + 255) / 256, 256>>>(b, out, M);
}